// round 4
// baseline (speedup 1.0000x reference)
#include <cuda_runtime.h>

// SparseConv1D: out[b,o,l] = sum_i sum_k w[o,i,k] * x[b,i,l+d_k] (zero pad OOR)
// x: [16,64,4096] f32, w: [64,64,32] f32, out: [16,64,4096] f32.
//
// FFMA2 lanes pair BATCHES: win[j] = (x[b0,i,g], x[b1,i,g]) so every tap
// offset is an aligned coalesced LDS.64 (no shifted copy, no parity cases).
// Window + weights double-buffered in smem: one barrier per input channel,
// next channel's LDGs issued before compute, STS placed mid-compute.

#define K_TAPS   32
#define CIN      64
#define COUT     64
#define LEN      4096
#define BATCH    16
#define LOWPAD   512
#define PAD      768                    // 512 low + 256 high
#define THREADS  128
#define NOUT     8
#define NPAIR    4
#define LTILE    (THREADS * NPAIR)      // 512 positions per block
#define WIN2     (LTILE + PAD)          // 1280 float2 window slots
#define FILL_IT  (WIN2 / 2 / THREADS)   // 5 (each it covers 2 slots/thread)

// Packed fp32x2 FMA (Blackwell FFMA2), PTX-only.
__device__ __forceinline__ float2 ffma2(float2 a, float2 b, float2 c) {
    float2 d;
    asm("fma.rn.f32x2 %0, %1, %2, %3;"
        : "=l"(*reinterpret_cast<unsigned long long*>(&d))
        : "l"(*reinterpret_cast<unsigned long long*>(&a)),
          "l"(*reinterpret_cast<unsigned long long*>(&b)),
          "l"(*reinterpret_cast<unsigned long long*>(&c)));
    return d;
}

__global__ __launch_bounds__(THREADS, 4)
void sk_conv_kernel(const float* __restrict__ x,
                    const float* __restrict__ w,
                    float* __restrict__ out) {
    constexpr int SK[K_TAPS] = {
        -512,-256,-128,-96,-64,-48,-32,-24,-16,-12,-8,-6,-4,-3,-2,-1,
         0,1,2,3,4,6,8,12,16,24,32,48,64,96,128,256
    };

    __shared__ float2 win[2][WIN2];            // 20 KB (batch-interleaved x)
    __shared__ float2 wdup[2][K_TAPS * NOUT];  // 4 KB  (weights, (w,w))

    const int tid = threadIdx.x;
    const int l0  = blockIdx.x * LTILE;
    const int o0  = blockIdx.y * NOUT;
    const int b0  = blockIdx.z * 2;

    const float* xb0 = x + (size_t)b0 * CIN * LEN;
    const float* xb1 = xb0 + (size_t)CIN * LEN;

    // weight lanes: thread covers elems tid and tid+128 of the 256-elem slice
    const int oA = (tid & 7), kA = tid >> 3;
    const int oB = ((tid + THREADS) & 7), kB = (tid + THREADS) >> 3;
    const float* wA = w + ((size_t)(o0 + oA) * CIN) * K_TAPS + kA;
    const float* wB = w + ((size_t)(o0 + oB) * CIN) * K_TAPS + kB;

    // ---- prologue: weights for i=0 staged, i=1 prefetched; window 0 filled
    {
        float w0a = __ldg(wA), w0b = __ldg(wB);
        wdup[0][tid]           = make_float2(w0a, w0a);
        wdup[0][tid + THREADS] = make_float2(w0b, w0b);
    }
    float wra = __ldg(wA + K_TAPS);
    float wrb = __ldg(wB + K_TAPS);

#pragma unroll
    for (int it = 0; it < FILL_IT; ++it) {
        int j2 = tid + it * THREADS;
        int g  = l0 - LOWPAD + 2 * j2;          // even
        float2 a = make_float2(0.f, 0.f), bb = make_float2(0.f, 0.f);
        if ((unsigned)g <= (unsigned)(LEN - 2)) {
            a  = *reinterpret_cast<const float2*>(xb0 + g);
            bb = *reinterpret_cast<const float2*>(xb1 + g);
        }
        win[0][2 * j2]     = make_float2(a.x, bb.x);
        win[0][2 * j2 + 1] = make_float2(a.y, bb.y);
    }
    __syncthreads();

    float2 acc[NOUT][NPAIR];
#pragma unroll
    for (int o = 0; o < NOUT; ++o)
#pragma unroll
        for (int p = 0; p < NPAIR; ++p) acc[o][p] = make_float2(0.f, 0.f);

    for (int i = 0; i < CIN; ++i) {
        const int cur = i & 1, nxt = cur ^ 1;
        const bool more = (i + 1 < CIN);

        // ---- stage next channel's x into registers (latency overlapped below)
        float2 sa[FILL_IT], sb[FILL_IT];
        if (more) {
            const float* xi0 = xb0 + (i + 1) * LEN;
            const float* xi1 = xb1 + (i + 1) * LEN;
#pragma unroll
            for (int it = 0; it < FILL_IT; ++it) {
                int j2 = tid + it * THREADS;
                int g  = l0 - LOWPAD + 2 * j2;
                sa[it] = make_float2(0.f, 0.f);
                sb[it] = make_float2(0.f, 0.f);
                if ((unsigned)g <= (unsigned)(LEN - 2)) {
                    sa[it] = *reinterpret_cast<const float2*>(xi0 + g);
                    sb[it] = *reinterpret_cast<const float2*>(xi1 + g);
                }
            }
        }

        // ---- compute taps 0..7 (covers LDG latency before the STS below)
#pragma unroll
        for (int k = 0; k < 8; ++k) {
            const int off = SK[k] + LOWPAD;
            float2 xv[NPAIR];
#pragma unroll
            for (int p = 0; p < NPAIR; ++p)
                xv[p] = win[cur][tid + THREADS * p + off];
#pragma unroll
            for (int o = 0; o < NOUT; ++o) {
                float2 wv = wdup[cur][k * NOUT + o];
#pragma unroll
                for (int p = 0; p < NPAIR; ++p)
                    acc[o][p] = ffma2(wv, xv[p], acc[o][p]);
            }
        }

        // ---- commit next buffers (x window + weights), prefetch w for i+2
        if (more) {
#pragma unroll
            for (int it = 0; it < FILL_IT; ++it) {
                int j2 = tid + it * THREADS;
                win[nxt][2 * j2]     = make_float2(sa[it].x, sb[it].x);
                win[nxt][2 * j2 + 1] = make_float2(sa[it].y, sb[it].y);
            }
            wdup[nxt][tid]           = make_float2(wra, wra);
            wdup[nxt][tid + THREADS] = make_float2(wrb, wrb);
            if (i + 2 < CIN) {
                wra = __ldg(wA + (i + 2) * K_TAPS);
                wrb = __ldg(wB + (i + 2) * K_TAPS);
            }
        }

        // ---- compute taps 8..31
#pragma unroll
        for (int k = 8; k < K_TAPS; ++k) {
            const int off = SK[k] + LOWPAD;
            float2 xv[NPAIR];
#pragma unroll
            for (int p = 0; p < NPAIR; ++p)
                xv[p] = win[cur][tid + THREADS * p + off];
#pragma unroll
            for (int o = 0; o < NOUT; ++o) {
                float2 wv = wdup[cur][k * NOUT + o];
#pragma unroll
                for (int p = 0; p < NPAIR; ++p)
                    acc[o][p] = ffma2(wv, xv[p], acc[o][p]);
            }
        }

        __syncthreads();   // one barrier per channel
    }

    // ---- store: lanes are (b0, b1) at the same (o, l)
#pragma unroll
    for (int o = 0; o < NOUT; ++o) {
        float* o0p = out + ((size_t)(b0)     * COUT + o0 + o) * LEN + l0;
        float* o1p = out + ((size_t)(b0 + 1) * COUT + o0 + o) * LEN + l0;
#pragma unroll
        for (int p = 0; p < NPAIR; ++p) {
            int l = tid + THREADS * p;
            o0p[l] = acc[o][p].x;
            o1p[l] = acc[o][p].y;
        }
    }
}

extern "C" void kernel_launch(void* const* d_in, const int* in_sizes, int n_in,
                              void* d_out, int out_size) {
    const float* x = (const float*)d_in[0];   // [16,64,4096]
    const float* w = (const float*)d_in[1];   // [64,64,32]
    float* out = (float*)d_out;               // [16,64,4096]
    dim3 grid(LEN / LTILE, COUT / NOUT, BATCH / 2);  // (8, 8, 8) = 512 blocks
    sk_conv_kernel<<<grid, THREADS>>>(x, w, out);
}

// round 5
// speedup vs baseline: 1.7565x; 1.7565x over previous
#include <cuda_runtime.h>

// SparseConv1D: out[b,o,l] = sum_i sum_k w[o,i,k] * x[b,i,l+d_k] (zero pad OOR)
// x: [16,64,4096] f32, w: [64,64,32] f32, out: [16,64,4096] f32.
//
// FFMA2 lanes pair BATCHES: win[j] = (x[b0,i,g], x[b1,i,g]) -> any tap offset
// is one aligned LDS.64. Weights staged per-channel as float4 (4 taps) and
// broadcast via LDS.128, lane-dup done by ALU MOVs. Crossbar budget per
// warp-tap: 8 cyc (x) + 2 cyc (w) = 10 < 16 fma-cyc -> fma-bound.

#define K_TAPS   32
#define CIN      64
#define COUT     64
#define LEN      4096
#define BATCH    16
#define LOWPAD   512
#define THREADS  128
#define NOUT     8
#define NPAIR    4
#define LTILE    (THREADS * NPAIR)      // 512 positions per block
#define WIN2     (LTILE + 768)          // 1280 float2 window slots
#define FILL_IT  (WIN2 / 2 / THREADS)   // 5

// Packed fp32x2 FMA (Blackwell FFMA2), PTX-only.
__device__ __forceinline__ float2 ffma2(float2 a, float2 b, float2 c) {
    float2 d;
    asm("fma.rn.f32x2 %0, %1, %2, %3;"
        : "=l"(*reinterpret_cast<unsigned long long*>(&d))
        : "l"(*reinterpret_cast<unsigned long long*>(&a)),
          "l"(*reinterpret_cast<unsigned long long*>(&b)),
          "l"(*reinterpret_cast<unsigned long long*>(&c)));
    return d;
}

__global__ __launch_bounds__(THREADS, 4)
void sk_conv_kernel(const float* __restrict__ x,
                    const float* __restrict__ w,
                    float* __restrict__ out) {
    constexpr int SK[K_TAPS] = {
        -512,-256,-128,-96,-64,-48,-32,-24,-16,-12,-8,-6,-4,-3,-2,-1,
         0,1,2,3,4,6,8,12,16,24,32,48,64,96,128,256
    };

    __shared__ float2 win[WIN2];                     // 10 KB
    __shared__ float4 wq[(K_TAPS / 4) * NOUT];       // 1 KB : [kk4][o] 4 taps

    const int tid = threadIdx.x;
    const int l0  = blockIdx.x * LTILE;
    const int o0  = blockIdx.y * NOUT;
    const int b0  = blockIdx.z * 2;

    const float* xp0 = x + (size_t)b0 * CIN * LEN;
    const float* xp1 = xp0 + (size_t)CIN * LEN;

    // weight staging lane (threads 0..63): wq[kk4*8+o] = w[o0+o, i, 4kk4..4kk4+3]
    const int so   = tid & 7;
    const int skk4 = tid >> 3;
    const float* wsrc = w + ((size_t)(o0 + so) * CIN) * K_TAPS + 4 * skk4;

    float4 wpre;
    if (tid < 64) wpre = *reinterpret_cast<const float4*>(wsrc);   // i = 0

    float2 acc[NOUT][NPAIR];
#pragma unroll
    for (int o = 0; o < NOUT; ++o)
#pragma unroll
        for (int p = 0; p < NPAIR; ++p) acc[o][p] = make_float2(0.f, 0.f);

    for (int i = 0; i < CIN; ++i) {
        __syncthreads();   // previous window + weights fully consumed

        // stage this channel's weights
        if (tid < 64) wq[skk4 * NOUT + so] = wpre;

        // fill batch-interleaved window (no register staging arrays)
        const float* xi0 = xp0 + i * LEN;
        const float* xi1 = xp1 + i * LEN;
#pragma unroll
        for (int it = 0; it < FILL_IT; ++it) {
            int j2 = tid + it * THREADS;
            int g  = l0 - LOWPAD + 2 * j2;          // always even
            float2 a = make_float2(0.f, 0.f), bb = make_float2(0.f, 0.f);
            if ((unsigned)g <= (unsigned)(LEN - 2)) {
                a  = *reinterpret_cast<const float2*>(xi0 + g);
                bb = *reinterpret_cast<const float2*>(xi1 + g);
            }
            win[2 * j2]     = make_float2(a.x, bb.x);
            win[2 * j2 + 1] = make_float2(a.y, bb.y);
        }

        // prefetch next channel's weights (hidden until next staging)
        if (tid < 64 && i + 1 < CIN)
            wpre = *reinterpret_cast<const float4*>(wsrc + (i + 1) * K_TAPS);

        __syncthreads();

        // ---- compute: 8 groups of 4 taps ----
#pragma unroll
        for (int kk4 = 0; kk4 < K_TAPS / 4; ++kk4) {
            float4 wv[NOUT];
#pragma unroll
            for (int o = 0; o < NOUT; ++o)
                wv[o] = wq[kk4 * NOUT + o];          // broadcast LDS.128

#pragma unroll
            for (int s = 0; s < 4; ++s) {
                const int off = SK[4 * kk4 + s] + LOWPAD;
                float2 xv[NPAIR];
#pragma unroll
                for (int p = 0; p < NPAIR; ++p)
                    xv[p] = win[tid + THREADS * p + off];
#pragma unroll
                for (int o = 0; o < NOUT; ++o) {
                    const float ws = (s == 0) ? wv[o].x :
                                     (s == 1) ? wv[o].y :
                                     (s == 2) ? wv[o].z : wv[o].w;
                    float2 wd = make_float2(ws, ws); // ALU dup
#pragma unroll
                    for (int p = 0; p < NPAIR; ++p)
                        acc[o][p] = ffma2(wd, xv[p], acc[o][p]);
                }
            }
        }
    }

    // ---- store: lanes are (b0, b1) at the same (o, l) ----
#pragma unroll
    for (int o = 0; o < NOUT; ++o) {
        float* q0 = out + ((size_t)(b0)     * COUT + o0 + o) * LEN + l0;
        float* q1 = out + ((size_t)(b0 + 1) * COUT + o0 + o) * LEN + l0;
#pragma unroll
        for (int p = 0; p < NPAIR; ++p) {
            int l = tid + THREADS * p;
            q0[l] = acc[o][p].x;
            q1[l] = acc[o][p].y;
        }
    }
}

extern "C" void kernel_launch(void* const* d_in, const int* in_sizes, int n_in,
                              void* d_out, int out_size) {
    const float* x = (const float*)d_in[0];   // [16,64,4096]
    const float* w = (const float*)d_in[1];   // [64,64,32]
    float* out = (float*)d_out;               // [16,64,4096]
    dim3 grid(LEN / LTILE, COUT / NOUT, BATCH / 2);  // (8, 8, 8) = 512 blocks
    sk_conv_kernel<<<grid, THREADS>>>(x, w, out);
}

// round 7
// speedup vs baseline: 1.8922x; 1.0773x over previous
#include <cuda_runtime.h>
#include <cstdint>

// SparseConv1D: out[b,o,l] = sum_i sum_k w[o,i,k] * x[b,i,l+d_k] (zero pad OOR)
// x: [16,64,4096] f32, w: [64,64,32] f32, out: [16,64,4096] f32.
//
// Two kernels in one graph:
//  1) prepass: build padded, batch-interleaved copy of x in __device__ scratch:
//     g_xi[bp][i][j] = (x[2bp,i,j-512], x[2bp+1,i,j-512]), zeros outside.
//  2) main: per input channel, cp.async (LDGSTS) the 1280-float2 window slice
//     into a double-buffered smem window while computing the current channel.
//     FFMA2 lanes pair batches -> every tap offset is one aligned LDS.64.

#define K_TAPS   32
#define CIN      64
#define COUT     64
#define LEN      4096
#define BATCH    16
#define LOWPAD   512
#define PADLEN   (LEN + 768)            // 4864 padded slots
#define THREADS  128
#define NOUT     8
#define NPAIR    4
#define LTILE    (THREADS * NPAIR)      // 512 positions per block
#define WIN2     (LTILE + 768)          // 1280 float2 window slots
#define CHUNKS   (WIN2 * 8 / 16)        // 640 16B cp.async chunks
#define NBP      (BATCH / 2)            // 8 batch pairs

__device__ __align__(16) float2 g_xi[NBP * CIN * PADLEN];   // ~19.9 MB

// Packed fp32x2 FMA (Blackwell FFMA2), PTX-only.
__device__ __forceinline__ float2 ffma2(float2 a, float2 b, float2 c) {
    float2 d;
    asm("fma.rn.f32x2 %0, %1, %2, %3;"
        : "=l"(*reinterpret_cast<unsigned long long*>(&d))
        : "l"(*reinterpret_cast<unsigned long long*>(&a)),
          "l"(*reinterpret_cast<unsigned long long*>(&b)),
          "l"(*reinterpret_cast<unsigned long long*>(&c)));
    return d;
}

__device__ __forceinline__ void cp_async16(unsigned int dst_smem, const void* src) {
    asm volatile("cp.async.cg.shared.global [%0], [%1], 16;"
                 :: "r"(dst_smem), "l"(src));
}
__device__ __forceinline__ void cp_async_commit() {
    asm volatile("cp.async.commit_group;");
}
__device__ __forceinline__ void cp_async_wait_all() {
    asm volatile("cp.async.wait_group 0;");
}
__device__ __forceinline__ unsigned int smem_u32(const void* p) {
    unsigned int a;
    asm("{ .reg .u64 t; cvta.to.shared.u64 t, %1; cvt.u32.u64 %0, t; }"
        : "=r"(a) : "l"(p));
    return a;
}

// ---- prepass: pad + batch-interleave x --------------------------------
__global__ void interleave_kernel(const float* __restrict__ x) {
    int idx = blockIdx.x * blockDim.x + threadIdx.x;     // over NBP*CIN*PADLEN
    if (idx >= NBP * CIN * PADLEN) return;
    int j  = idx % PADLEN;
    int ci = idx / PADLEN;          // bp*CIN + i
    int bp = ci / CIN;
    int g  = j - LOWPAD;
    float a = 0.f, b = 0.f;
    if ((unsigned)g < (unsigned)LEN) {
        const float* base = x + ((size_t)(2 * bp) * CIN + (ci % CIN)) * LEN + g;
        a = base[0];
        b = base[CIN * LEN];
    }
    g_xi[idx] = make_float2(a, b);
}

// ---- main kernel -------------------------------------------------------
__global__ __launch_bounds__(THREADS, 4)
void sk_conv_kernel(const float* __restrict__ w,
                    float* __restrict__ out) {
    constexpr int SK[K_TAPS] = {
        -512,-256,-128,-96,-64,-48,-32,-24,-16,-12,-8,-6,-4,-3,-2,-1,
         0,1,2,3,4,6,8,12,16,24,32,48,64,96,128,256
    };

    __shared__ __align__(16) float2 win[2][WIN2];          // 20 KB
    __shared__ float4 wq[2][(K_TAPS / 4) * NOUT];          // 2 KB

    const int tid = threadIdx.x;
    const int l0  = blockIdx.x * LTILE;
    const int o0  = blockIdx.y * NOUT;
    const int bp  = blockIdx.z;

    const float2* xrow = g_xi + ((size_t)bp * CIN) * PADLEN + l0;
    const unsigned int win_s0 = smem_u32(&win[0][0]);
    const unsigned int win_s1 = smem_u32(&win[1][0]);

    // weight staging lane (threads 0..63): wq[.][kk4*8+o] = w[o0+o,i,4kk4..+3]
    const int so   = tid & 7;
    const int skk4 = tid >> 3;
    const float* wsrc = w + ((size_t)(o0 + so) * CIN) * K_TAPS + 4 * skk4;

    // ---- prologue: window 0 + weights for i=0; prefetch weights i=1 ----
#pragma unroll
    for (int it = 0; it < CHUNKS / THREADS; ++it) {
        int c = tid + it * THREADS;
        cp_async16(win_s0 + c * 16, (const char*)xrow + c * 16);
    }
    cp_async_commit();

    float4 wpre1;
    if (tid < 64) {
        float4 wpre0 = *reinterpret_cast<const float4*>(wsrc);     // i=0
        wpre1 = *reinterpret_cast<const float4*>(wsrc + K_TAPS);   // i=1
        wq[0][skk4 * NOUT + so] = wpre0;
    }
    cp_async_wait_all();
    __syncthreads();

    float2 acc[NOUT][NPAIR];
#pragma unroll
    for (int o = 0; o < NOUT; ++o)
#pragma unroll
        for (int p = 0; p < NPAIR; ++p) acc[o][p] = make_float2(0.f, 0.f);

    for (int i = 0; i < CIN; ++i) {
        const int cur = i & 1, nxt = cur ^ 1;
        const bool more = (i + 1 < CIN);

        // ---- launch async fill of next channel's window + stage weights
        if (more) {
            const char* src = (const char*)(xrow + (size_t)(i + 1) * PADLEN);
            const unsigned int dst = nxt ? win_s1 : win_s0;
#pragma unroll
            for (int it = 0; it < CHUNKS / THREADS; ++it) {
                int c = tid + it * THREADS;
                cp_async16(dst + c * 16, src + c * 16);
            }
            cp_async_commit();
            if (tid < 64) {
                wq[nxt][skk4 * NOUT + so] = wpre1;
                if (i + 2 < CIN)
                    wpre1 = *reinterpret_cast<const float4*>(
                        wsrc + (i + 2) * K_TAPS);
            }
        }

        // ---- compute current channel: 8 groups of 4 taps ----
#pragma unroll
        for (int kk4 = 0; kk4 < K_TAPS / 4; ++kk4) {
            float4 wv[NOUT];
#pragma unroll
            for (int o = 0; o < NOUT; ++o)
                wv[o] = wq[cur][kk4 * NOUT + o];     // broadcast LDS.128

#pragma unroll
            for (int s = 0; s < 4; ++s) {
                const int off = SK[4 * kk4 + s] + LOWPAD;
                float2 xv[NPAIR];
#pragma unroll
                for (int p = 0; p < NPAIR; ++p)
                    xv[p] = win[cur][tid + THREADS * p + off];
#pragma unroll
                for (int o = 0; o < NOUT; ++o) {
                    const float ws = (s == 0) ? wv[o].x :
                                     (s == 1) ? wv[o].y :
                                     (s == 2) ? wv[o].z : wv[o].w;
                    float2 wd = make_float2(ws, ws);  // ALU dup
#pragma unroll
                    for (int p = 0; p < NPAIR; ++p)
                        acc[o][p] = ffma2(wd, xv[p], acc[o][p]);
                }
            }
        }

        if (more) cp_async_wait_all();
        __syncthreads();     // one barrier per channel
    }

    // ---- store: lanes are (b0, b1) at the same (o, l) ----
    const int b0 = bp * 2;
#pragma unroll
    for (int o = 0; o < NOUT; ++o) {
        float* q0 = out + ((size_t)(b0)     * COUT + o0 + o) * LEN + l0;
        float* q1 = out + ((size_t)(b0 + 1) * COUT + o0 + o) * LEN + l0;
#pragma unroll
        for (int p = 0; p < NPAIR; ++p) {
            int l = tid + THREADS * p;
            q0[l] = acc[o][p].x;
            q1[l] = acc[o][p].y;
        }
    }
}

extern "C" void kernel_launch(void* const* d_in, const int* in_sizes, int n_in,
                              void* d_out, int out_size) {
    const float* x = (const float*)d_in[0];   // [16,64,4096]
    const float* w = (const float*)d_in[1];   // [64,64,32]
    float* out = (float*)d_out;               // [16,64,4096]

    int total = NBP * CIN * PADLEN;
    interleave_kernel<<<(total + 255) / 256, 256>>>(x);

    dim3 grid(LEN / LTILE, COUT / NOUT, NBP);  // (8, 8, 8) = 512 blocks
    sk_conv_kernel<<<grid, THREADS>>>(w, out);
}